// round 7
// baseline (speedup 1.0000x reference)
#include <cuda_runtime.h>
#include <cuda_bf16.h>
#include <math.h>
#include <stdint.h>

#define T_STEPS 1024
#define BATCH   32
#define INP     512
#define HID     512
#define G4      2048   // 4*HID
#define MTOT    (T_STEPS * BATCH)   // 32768

// ---------------- scratch ----------------
__device__ float g_xw[(size_t)T_STEPS * G4 * BATCH]; // [t][col][b]  (256 MB)
__device__ __nv_bfloat16 g_xhi[(size_t)MTOT * INP];  // x hi  [m][k]
__device__ __nv_bfloat16 g_xlo[(size_t)MTOT * INP];  // x lo
__device__ __nv_bfloat16 g_whi[(size_t)G4 * INP];    // W^T hi [n][k]
__device__ __nv_bfloat16 g_wlo[(size_t)G4 * INP];    // W^T lo
__device__ __nv_bfloat16 g_hb[2][2][BATCH * HID];    // h ping-pong [ping][hi/lo][b*512+k]
__device__ unsigned int g_cflag[8];                  // per-chunk producer counters

// ================= helpers =================
__device__ __forceinline__ uint32_t smem_to_u32(const void* p) {
    uint32_t a;
    asm("{ .reg .u64 t; cvta.to.shared.u64 t, %1; cvt.u32.u64 %0, t; }"
        : "=r"(a) : "l"(p));
    return a;
}
#define SMEM_SWIZZLE_128B(off) ((off) ^ (((off) >> 3) & 0x70))

__device__ __forceinline__ void cp_async16(uint32_t smem_addr, const void* gptr) {
    asm volatile("cp.async.cg.shared.global [%0], [%1], 16;"
                 :: "r"(smem_addr), "l"(gptr) : "memory");
}
__device__ __forceinline__ void cp_async_commit() {
    asm volatile("cp.async.commit_group;" ::: "memory");
}
template <int N>
__device__ __forceinline__ void cp_async_wait() {
    asm volatile("cp.async.wait_group %0;" :: "n"(N) : "memory");
}

__device__ __forceinline__ void ldmatrix_x4(uint32_t* r, uint32_t addr) {
    asm volatile("ldmatrix.sync.aligned.m8n8.x4.shared.b16 {%0,%1,%2,%3}, [%4];"
                 : "=r"(r[0]), "=r"(r[1]), "=r"(r[2]), "=r"(r[3]) : "r"(addr));
}
__device__ __forceinline__ void mma_bf16(float* c, const uint32_t* a, const uint32_t* b) {
    asm volatile(
        "mma.sync.aligned.m16n8k16.row.col.f32.bf16.bf16.f32 "
        "{%0,%1,%2,%3}, {%4,%5,%6,%7}, {%8,%9}, {%0,%1,%2,%3};"
        : "+f"(c[0]), "+f"(c[1]), "+f"(c[2]), "+f"(c[3])
        : "r"(a[0]), "r"(a[1]), "r"(a[2]), "r"(a[3]), "r"(b[0]), "r"(b[1]));
}
__device__ __forceinline__ float sigmoidf_(float v) {
    return 1.f / (1.f + __expf(-v));
}

// ---------------- init ----------------
__global__ void lstm_init_kernel() {
    int idx = blockIdx.x * blockDim.x + threadIdx.x;
    int n = 2 * 2 * BATCH * HID;
    __nv_bfloat16 z = __float2bfloat16(0.f);
    for (int i = idx; i < n; i += gridDim.x * blockDim.x)
        ((__nv_bfloat16*)g_hb)[i] = z;
    if (idx < 8) g_cflag[idx] = 0u;
}

// ---------------- convert x -> bf16 hi/lo ----------------
__global__ __launch_bounds__(256) void xcvt_kernel(const float* __restrict__ x) {
    size_t i = ((size_t)blockIdx.x * 256 + threadIdx.x) * 4;
    float4 v = *(const float4*)(x + i);
    __nv_bfloat16 h0 = __float2bfloat16(v.x), h1 = __float2bfloat16(v.y),
                  h2 = __float2bfloat16(v.z), h3 = __float2bfloat16(v.w);
    __nv_bfloat16 l0 = __float2bfloat16(v.x - __bfloat162float(h0));
    __nv_bfloat16 l1 = __float2bfloat16(v.y - __bfloat162float(h1));
    __nv_bfloat16 l2 = __float2bfloat16(v.z - __bfloat162float(h2));
    __nv_bfloat16 l3 = __float2bfloat16(v.w - __bfloat162float(h3));
    __nv_bfloat162* ph = (__nv_bfloat162*)(g_xhi + i);
    __nv_bfloat162* pl = (__nv_bfloat162*)(g_xlo + i);
    ph[0] = __nv_bfloat162(h0, h1); ph[1] = __nv_bfloat162(h2, h3);
    pl[0] = __nv_bfloat162(l0, l1); pl[1] = __nv_bfloat162(l2, l3);
}

// ---------------- convert + transpose W -> [n][k] bf16 hi/lo ----------------
__global__ __launch_bounds__(256) void wcvt_kernel(const float* __restrict__ W) {
    __shared__ float tile[32][33];
    int n0 = blockIdx.x * 32, k0 = blockIdx.y * 32;
    int tx = threadIdx.x & 31, ty = threadIdx.x >> 5;   // 32 x 8
    #pragma unroll
    for (int r = 0; r < 4; r++)
        tile[ty + 8 * r][tx] = W[(size_t)(k0 + ty + 8 * r) * G4 + n0 + tx];
    __syncthreads();
    #pragma unroll
    for (int r = 0; r < 4; r++) {
        float v = tile[tx][ty + 8 * r];
        __nv_bfloat16 hi = __float2bfloat16(v);
        __nv_bfloat16 lo = __float2bfloat16(v - __bfloat162float(hi));
        size_t o = (size_t)(n0 + ty + 8 * r) * INP + k0 + tx;
        g_whi[o] = hi;
        g_wlo[o] = lo;
    }
}

// ---------------- phase 1: mma.sync bf16 hi/lo GEMM (unchanged) ----------------
#define GEMM_SMEM_BYTES (1024 + 2 * 65536)

__global__ __launch_bounds__(256, 1) void xw_tc_kernel(const float* __restrict__ bias)
{
    extern __shared__ char smem[];
    const uint32_t sb = smem_to_u32(smem);
    const int tid  = threadIdx.x;
    const int wid  = tid >> 5;
    const int lane = tid & 31;
    const int n0 = blockIdx.x * 128;
    const int m0 = blockIdx.y * 128;
    float* bias_sm = (float*)smem;

    if (tid < 128) bias_sm[tid] = bias[n0 + tid];

    const int wm = (wid & 1) * 64;
    const int wn = (wid >> 1) * 32;

    const uint32_t aRow = (uint32_t)(lane & 15);
    const uint32_t aCol = (uint32_t)(((lane >> 4) & 1) * 16);
    const uint32_t bRow = (uint32_t)(((lane >> 4) & 1) * 8 + (lane & 7));
    const uint32_t bCol = (uint32_t)(((lane >> 3) & 1) * 16);

    uint32_t aOff[4], bOff[2];
    #pragma unroll
    for (int im = 0; im < 4; im++)
        aOff[im] = (uint32_t)(wm + 16 * im + aRow) * 128 + aCol;
    #pragma unroll
    for (int in_ = 0; in_ < 2; in_++)
        bOff[in_] = (uint32_t)(wn + 16 * in_ + bRow) * 128 + bCol;

    float c[4][4][4];
    #pragma unroll
    for (int i = 0; i < 4; i++)
        #pragma unroll
        for (int j = 0; j < 4; j++)
            #pragma unroll
            for (int k = 0; k < 4; k++) c[i][j][k] = 0.f;

    const int lrow0 = tid >> 3;
    const int lc16  = tid & 7;

    auto issue_chunk = [&](int ch, int buf) {
        const uint32_t bbase = 1024u + (uint32_t)buf * 65536u;
        const int kb = ch * 64;
        #pragma unroll
        for (int it = 0; it < 4; it++) {
            int row = lrow0 + it * 32;
            uint32_t sw = SMEM_SWIZZLE_128B((uint32_t)(row * 128 + lc16 * 16));
            const __nv_bfloat16* gA = g_xhi + (size_t)(m0 + row) * INP + kb + lc16 * 8;
            const __nv_bfloat16* gAl= g_xlo + (size_t)(m0 + row) * INP + kb + lc16 * 8;
            const __nv_bfloat16* gB = g_whi + (size_t)(n0 + row) * INP + kb + lc16 * 8;
            const __nv_bfloat16* gBl= g_wlo + (size_t)(n0 + row) * INP + kb + lc16 * 8;
            cp_async16(sb + bbase +         sw, gA);
            cp_async16(sb + bbase + 16384 + sw, gAl);
            cp_async16(sb + bbase + 32768 + sw, gB);
            cp_async16(sb + bbase + 49152 + sw, gBl);
        }
        cp_async_commit();
    };

    issue_chunk(0, 0);

    for (int ch = 0; ch < 8; ch++) {
        const int buf = ch & 1;
        if (ch < 7) issue_chunk(ch + 1, buf ^ 1);
        if (ch < 7) cp_async_wait<1>(); else cp_async_wait<0>();
        __syncthreads();

        const uint32_t bbase = sb + 1024u + (uint32_t)buf * 65536u;
        #pragma unroll
        for (int ks = 0; ks < 4; ks++) {
            uint32_t ahi[4][4], alo[4][4], bhi[4][4], blo[4][4];
            #pragma unroll
            for (int im = 0; im < 4; im++) {
                uint32_t sw = SMEM_SWIZZLE_128B(aOff[im] + ks * 32);
                ldmatrix_x4(ahi[im], bbase + sw);
                ldmatrix_x4(alo[im], bbase + 16384 + sw);
            }
            #pragma unroll
            for (int ib = 0; ib < 2; ib++) {
                uint32_t sw = SMEM_SWIZZLE_128B(bOff[ib] + ks * 32);
                ldmatrix_x4(bhi[ib], bbase + 32768 + sw);
                ldmatrix_x4(blo[ib], bbase + 49152 + sw);
            }
            #pragma unroll
            for (int im = 0; im < 4; im++) {
                #pragma unroll
                for (int jn = 0; jn < 4; jn++) {
                    uint32_t* bh = &bhi[jn >> 1][(jn & 1) * 2];
                    uint32_t* bl = &blo[jn >> 1][(jn & 1) * 2];
                    mma_bf16(c[im][jn], ahi[im], bh);
                    mma_bf16(c[im][jn], ahi[im], bl);
                    mma_bf16(c[im][jn], alo[im], bh);
                }
            }
        }
        __syncthreads();
    }

    float* cs = (float*)(smem + 1024);   // [128][129]
    const int crow = lane >> 2;
    const int ccol = (lane & 3) * 2;
    #pragma unroll
    for (int im = 0; im < 4; im++) {
        #pragma unroll
        for (int jn = 0; jn < 4; jn++) {
            int r0 = wm + 16 * im + crow;
            int cc = wn + 8 * jn + ccol;
            cs[r0 * 129 + cc]           = c[im][jn][0];
            cs[r0 * 129 + cc + 1]       = c[im][jn][1];
            cs[(r0 + 8) * 129 + cc]     = c[im][jn][2];
            cs[(r0 + 8) * 129 + cc + 1] = c[im][jn][3];
        }
    }
    __syncthreads();

    const int t0 = blockIdx.y * 4;
    for (int i = 0; i < 64; i++) {
        int ro = wid * 64 + i;
        int tl = ro >> 7, n = ro & 127;
        float v = cs[(tl * 32 + lane) * 129 + n] + bias_sm[n];
        g_xw[((size_t)(t0 + tl) * G4 + n0 + n) * BATCH + lane] = v;
    }
}

// ---------------- phase 2: recurrence with per-chunk dataflow flags ------------
// 128 CTAs x 256 threads (8 warps). CTA owns 4 hidden units -> 16 gate cols.
// Warp w owns K-chunk w: waits flag[w] >= 16*t, loads, consumes.
// Producers: CTA bid contributes h units [4bid,4bid+4) -> chunk bid>>4; after
// writing h(t+1) it does red.release.gpu.add(flag[bid>>4], 1).
// 2-slot h ping-pong stays safe: a CTA reaching its write phase has seen all
// flags >= 16t => all CTAs finished step t-1 writes => finished step t-1 reads
// of the slot being overwritten.
#define R_HHI 0
#define R_HLO 32768
#define R_UHI 65536
#define R_ULO 81920
#define R_XW  98304
#define R_P   102400
#define REC2_SMEM_BYTES 120832
#define NCTA  128

__global__ __launch_bounds__(256, 1) void lstm_rec_tc_kernel(
    const float* __restrict__ U, float* __restrict__ out, int write_tail)
{
    extern __shared__ char smem[];
    const uint32_t sb = smem_to_u32(smem);
    const int tid  = threadIdx.x;
    const int wid  = tid >> 5;
    const int lane = tid & 31;
    const int u0   = blockIdx.x * 4;

    // ---- load U slice -> smem bf16 hi/lo, chunked+swizzled ----
    for (int i = tid; i < 16 * HID; i += 256) {
        int k = i >> 4, n = i & 15;
        int gcol = u0 + (n & 3) + 512 * (n >> 2);
        float v = U[(size_t)k * G4 + gcol];
        __nv_bfloat16 hi = __float2bfloat16(v);
        __nv_bfloat16 lo = __float2bfloat16(v - __bfloat162float(hi));
        int c = k >> 6, ko = k & 63;
        uint32_t sw = SMEM_SWIZZLE_128B((uint32_t)(n * 128 + ko * 2));
        *(__nv_bfloat16*)(smem + R_UHI + c * 2048 + sw) = hi;
        *(__nv_bfloat16*)(smem + R_ULO + c * 2048 + sw) = lo;
    }

    // ldmatrix lane address parts
    const uint32_t aRow = (uint32_t)(lane & 15);
    const uint32_t aCol = (uint32_t)(((lane >> 4) & 1) * 16);
    const uint32_t bRow = (uint32_t)(((lane >> 4) & 1) * 8 + (lane & 7));
    const uint32_t bCol = (uint32_t)(((lane >> 3) & 1) * 16);
    uint32_t aBase[2];
    #pragma unroll
    for (int mt = 0; mt < 2; mt++) aBase[mt] = (uint32_t)(mt * 16 + aRow) * 128 + aCol;
    const uint32_t bBase = bRow * 128 + bCol;

    // reduce mapping: thread (tid<128) owns (b = tid>>2, u = tid&3)
    const int rb = tid >> 2;
    const int ua = tid & 3;
    float c_state = 0.f;

    float* p_sm = (float*)(smem + R_P);
    unsigned int* myflag = &g_cflag[wid];

    // xw prefetch: warps 4-7 (threads 128..255), slot = t&1
    auto issue_xw = [&](int t) {
        if (tid >= 128) {
            int idx = tid - 128;
            int n = idx >> 3, seg = idx & 7;
            int gcol = u0 + (n & 3) + 512 * (n >> 2);
            cp_async16(sb + R_XW + (uint32_t)((t & 1) * 2048 + n * 128 + seg * 16),
                       g_xw + ((size_t)t * G4 + gcol) * BATCH + seg * 4);
            cp_async_commit();
        }
    };
    // h chunk load: warp w loads chunk w (its own cp.asyncs)
    auto issue_h_chunk = [&](int R, int cc) {
        const __nv_bfloat16* hhi = g_hb[R][0];
        const __nv_bfloat16* hlo = g_hb[R][1];
        #pragma unroll
        for (int j = 0; j < 8; j++) {
            int idx = lane + 32 * j;
            int b = idx >> 3, seg = idx & 7;
            uint32_t sw = SMEM_SWIZZLE_128B((uint32_t)(b * 128 + seg * 16));
            cp_async16(sb + R_HHI + cc * 4096 + sw, hhi + b * 512 + cc * 64 + seg * 8);
            cp_async16(sb + R_HLO + cc * 4096 + sw, hlo + b * 512 + cc * 64 + seg * 8);
        }
        cp_async_commit();
    };

    __syncthreads();            // U slice ready
    issue_xw(0);

    for (int t = 0; t < T_STEPS; t++) {
        const int R = t & 1;

        // wait for this warp's chunk producers (all lanes spin; acquire orders
        // each lane's own subsequent cp.asyncs)
        if (t > 0) {
            const unsigned int target = 16u * (unsigned int)t;
            unsigned int v;
            do {
                asm volatile("ld.acquire.gpu.u32 %0, [%1];"
                             : "=r"(v) : "l"(myflag) : "memory");
            } while (v < target);
        }

        issue_h_chunk(R, wid);

        float cfr[2][2][4];
        #pragma unroll
        for (int mt = 0; mt < 2; mt++)
            #pragma unroll
            for (int jn = 0; jn < 2; jn++)
                #pragma unroll
                for (int q = 0; q < 4; q++) cfr[mt][jn][q] = 0.f;

        cp_async_wait<0>();

        const uint32_t hbse = sb + R_HHI + wid * 4096;
        const uint32_t ubse = sb + R_UHI + wid * 2048;
        #pragma unroll
        for (int kt = 0; kt < 4; kt++) {
            uint32_t ahi[2][4], alo[2][4], bhi[4], blo[4];
            #pragma unroll
            for (int mt = 0; mt < 2; mt++) {
                uint32_t sw = SMEM_SWIZZLE_128B(aBase[mt] + kt * 32);
                ldmatrix_x4(ahi[mt], hbse + sw);
                ldmatrix_x4(alo[mt], hbse + 32768 + sw);
            }
            {
                uint32_t sw = SMEM_SWIZZLE_128B(bBase + kt * 32);
                ldmatrix_x4(bhi, ubse + sw);
                ldmatrix_x4(blo, ubse + 16384 + sw);
            }
            #pragma unroll
            for (int mt = 0; mt < 2; mt++) {
                #pragma unroll
                for (int jn = 0; jn < 2; jn++) {
                    uint32_t* bh = &bhi[jn * 2];
                    uint32_t* bl = &blo[jn * 2];
                    mma_bf16(cfr[mt][jn], ahi[mt], bh);
                    mma_bf16(cfr[mt][jn], ahi[mt], bl);
                    mma_bf16(cfr[mt][jn], alo[mt], bh);
                }
            }
        }

        // write K-partials to smem [w][m][18]
        {
            const int m  = lane >> 2;
            const int nn = 2 * (lane & 3);
            #pragma unroll
            for (int mt = 0; mt < 2; mt++) {
                #pragma unroll
                for (int jn = 0; jn < 2; jn++) {
                    int row = wid * 32 + mt * 16 + m;
                    int col = jn * 8 + nn;
                    *(float2*)&p_sm[row * 18 + col] =
                        make_float2(cfr[mt][jn][0], cfr[mt][jn][1]);
                    *(float2*)&p_sm[(row + 8) * 18 + col] =
                        make_float2(cfr[mt][jn][2], cfr[mt][jn][3]);
                }
            }
        }
        __syncthreads();   // partials + xw(t) visible; all warps past flag wait

        // prefetch xw for next step (different slot than the one being read)
        if (t + 1 < T_STEPS) issue_xw(t + 1);

        // reduce + activations (tid < 128): thread owns (rb, ua)
        if (tid < 128) {
            const float* xw_sm = (const float*)(smem + R_XW + (t & 1) * 2048);
            float s[4];
            #pragma unroll
            for (int g = 0; g < 4; g++) {
                int n = g * 4 + ua;
                float v = xw_sm[n * 32 + rb];
                #pragma unroll
                for (int w = 0; w < 8; w++)
                    v += p_sm[(w * 32 + rb) * 18 + n];
                s[g] = v;
            }
            float ig = sigmoidf_(s[0]);
            float fg = sigmoidf_(s[1]);
            float gg = tanhf(s[2]);
            float og = sigmoidf_(s[3]);
            float cnew = fg * c_state + ig * gg;
            float hnew = og * tanhf(cnew);
            c_state = cnew;

            out[((size_t)t * BATCH + rb) * HID + u0 + ua] = hnew;
            __nv_bfloat16 hh = __float2bfloat16(hnew);
            __nv_bfloat16 hl = __float2bfloat16(hnew - __bfloat162float(hh));
            g_hb[R ^ 1][0][rb * 512 + u0 + ua] = hh;
            g_hb[R ^ 1][1][rb * 512 + u0 + ua] = hl;
            if (write_tail && t == T_STEPS - 1) {
                out[(size_t)T_STEPS * BATCH * HID + (size_t)rb * HID + u0 + ua] = hnew;
                out[(size_t)T_STEPS * BATCH * HID + BATCH * HID
                    + (size_t)rb * HID + u0 + ua] = cnew;
            }
        }
        __syncthreads();   // h stores complete before the release below

        // signal: this CTA's h(t+1) units (chunk bid>>4) are ready
        if (t + 1 < T_STEPS && tid == 0) {
            asm volatile("red.release.gpu.add.u32 [%0], %1;"
                         :: "l"(&g_cflag[blockIdx.x >> 4]), "r"(1u) : "memory");
        }
    }
}

// ---------------- launch ----------------
extern "C" void kernel_launch(void* const* d_in, const int* in_sizes, int n_in,
                              void* d_out, int out_size)
{
    const float* x    = (const float*)d_in[0]; // (T,B,I)
    const float* W    = (const float*)d_in[1]; // (I,4H)
    const float* U    = (const float*)d_in[2]; // (H,4H)
    const float* bias = (const float*)d_in[3]; // (4H,)
    float* out = (float*)d_out;

    const long long need_tail = (long long)T_STEPS * BATCH * HID + 2LL * BATCH * HID;
    int write_tail = ((long long)out_size >= need_tail) ? 1 : 0;

    static int configured = 0;
    if (!configured) {
        cudaFuncSetAttribute(xw_tc_kernel,
                             cudaFuncAttributeMaxDynamicSharedMemorySize,
                             GEMM_SMEM_BYTES);
        cudaFuncSetAttribute(lstm_rec_tc_kernel,
                             cudaFuncAttributeMaxDynamicSharedMemorySize,
                             REC2_SMEM_BYTES);
        configured = 1;
    }

    lstm_init_kernel<<<64, 256>>>();
    xcvt_kernel<<<(MTOT * INP) / 4 / 256, 256>>>(x);
    wcvt_kernel<<<dim3(G4 / 32, INP / 32), 256>>>(W);
    xw_tc_kernel<<<dim3(16, 256), 256, GEMM_SMEM_BYTES>>>(bias);
    lstm_rec_tc_kernel<<<NCTA, 256, REC2_SMEM_BYTES>>>(U, out, write_tail);
}

// round 8
// speedup vs baseline: 1.2144x; 1.2144x over previous
#include <cuda_runtime.h>
#include <cuda_bf16.h>
#include <math.h>
#include <stdint.h>

#define T_STEPS 1024
#define BATCH   32
#define INP     512
#define HID     512
#define G4      2048   // 4*HID
#define MTOT    (T_STEPS * BATCH)   // 32768

// ---------------- scratch ----------------
__device__ float g_xw[(size_t)T_STEPS * G4 * BATCH]; // [t][col][b]  (256 MB)
__device__ __nv_bfloat16 g_xhi[(size_t)MTOT * INP];  // x hi  [m][k]
__device__ __nv_bfloat16 g_xlo[(size_t)MTOT * INP];  // x lo
__device__ __nv_bfloat16 g_whi[(size_t)G4 * INP];    // W^T hi [n][k]
__device__ __nv_bfloat16 g_wlo[(size_t)G4 * INP];    // W^T lo
__device__ signed char g_hq[2][32 * 1024];           // h 2-limb int8 ping-pong:
                                                     // [ping][b*1024 + c*128 + limb*64 + ko]
__device__ unsigned int g_bar;                       // grid barrier counter
__device__ unsigned int g_umax_bits;                 // max|U| as uint bits

// ================= helpers =================
__device__ __forceinline__ uint32_t smem_to_u32(const void* p) {
    uint32_t a;
    asm("{ .reg .u64 t; cvta.to.shared.u64 t, %1; cvt.u32.u64 %0, t; }"
        : "=r"(a) : "l"(p));
    return a;
}
#define SMEM_SWIZZLE_128B(off) ((off) ^ (((off) >> 3) & 0x70))

__device__ __forceinline__ void cp_async16(uint32_t smem_addr, const void* gptr) {
    asm volatile("cp.async.cg.shared.global [%0], [%1], 16;"
                 :: "r"(smem_addr), "l"(gptr) : "memory");
}
__device__ __forceinline__ void cp_async_commit() {
    asm volatile("cp.async.commit_group;" ::: "memory");
}
template <int N>
__device__ __forceinline__ void cp_async_wait() {
    asm volatile("cp.async.wait_group %0;" :: "n"(N) : "memory");
}

__device__ __forceinline__ void ldmatrix_x4(uint32_t* r, uint32_t addr) {
    asm volatile("ldmatrix.sync.aligned.m8n8.x4.shared.b16 {%0,%1,%2,%3}, [%4];"
                 : "=r"(r[0]), "=r"(r[1]), "=r"(r[2]), "=r"(r[3]) : "r"(addr));
}
__device__ __forceinline__ void mma_bf16(float* c, const uint32_t* a, const uint32_t* b) {
    asm volatile(
        "mma.sync.aligned.m16n8k16.row.col.f32.bf16.bf16.f32 "
        "{%0,%1,%2,%3}, {%4,%5,%6,%7}, {%8,%9}, {%0,%1,%2,%3};"
        : "+f"(c[0]), "+f"(c[1]), "+f"(c[2]), "+f"(c[3])
        : "r"(a[0]), "r"(a[1]), "r"(a[2]), "r"(a[3]), "r"(b[0]), "r"(b[1]));
}
__device__ __forceinline__ void mma_s8(int* c, const uint32_t* a, const uint32_t* b) {
    asm volatile(
        "mma.sync.aligned.m16n8k32.row.col.s32.s8.s8.s32 "
        "{%0,%1,%2,%3}, {%4,%5,%6,%7}, {%8,%9}, {%0,%1,%2,%3};"
        : "+r"(c[0]), "+r"(c[1]), "+r"(c[2]), "+r"(c[3])
        : "r"(a[0]), "r"(a[1]), "r"(a[2]), "r"(a[3]), "r"(b[0]), "r"(b[1]));
}
__device__ __forceinline__ float sigmoidf_(float v) {
    return 1.f / (1.f + __expf(-v));
}

// ---------------- init ----------------
__global__ void lstm_init_kernel() {
    int idx = blockIdx.x * blockDim.x + threadIdx.x;
    int n = 2 * 32 * 1024 / 4;
    for (int i = idx; i < n; i += gridDim.x * blockDim.x)
        ((int*)g_hq)[i] = 0;
    if (idx == 0) { g_bar = 0u; g_umax_bits = 0u; }
}

// ---------------- max|U| reduction ----------------
__global__ __launch_bounds__(256) void umax_kernel(const float* __restrict__ U) {
    __shared__ float red[256];
    float m = 0.f;
    int n = G4 * INP;
    for (int i = blockIdx.x * 256 + threadIdx.x; i < n; i += gridDim.x * 256)
        m = fmaxf(m, fabsf(U[i]));
    red[threadIdx.x] = m;
    __syncthreads();
    for (int s = 128; s > 0; s >>= 1) {
        if (threadIdx.x < s) red[threadIdx.x] = fmaxf(red[threadIdx.x], red[threadIdx.x + s]);
        __syncthreads();
    }
    if (threadIdx.x == 0)
        atomicMax(&g_umax_bits, __float_as_uint(red[0]));
}

// ---------------- convert x -> bf16 hi/lo ----------------
__global__ __launch_bounds__(256) void xcvt_kernel(const float* __restrict__ x) {
    size_t i = ((size_t)blockIdx.x * 256 + threadIdx.x) * 4;
    float4 v = *(const float4*)(x + i);
    __nv_bfloat16 h0 = __float2bfloat16(v.x), h1 = __float2bfloat16(v.y),
                  h2 = __float2bfloat16(v.z), h3 = __float2bfloat16(v.w);
    __nv_bfloat16 l0 = __float2bfloat16(v.x - __bfloat162float(h0));
    __nv_bfloat16 l1 = __float2bfloat16(v.y - __bfloat162float(h1));
    __nv_bfloat16 l2 = __float2bfloat16(v.z - __bfloat162float(h2));
    __nv_bfloat16 l3 = __float2bfloat16(v.w - __bfloat162float(h3));
    __nv_bfloat162* ph = (__nv_bfloat162*)(g_xhi + i);
    __nv_bfloat162* pl = (__nv_bfloat162*)(g_xlo + i);
    ph[0] = __nv_bfloat162(h0, h1); ph[1] = __nv_bfloat162(h2, h3);
    pl[0] = __nv_bfloat162(l0, l1); pl[1] = __nv_bfloat162(l2, l3);
}

// ---------------- convert + transpose W -> [n][k] bf16 hi/lo ----------------
__global__ __launch_bounds__(256) void wcvt_kernel(const float* __restrict__ W) {
    __shared__ float tile[32][33];
    int n0 = blockIdx.x * 32, k0 = blockIdx.y * 32;
    int tx = threadIdx.x & 31, ty = threadIdx.x >> 5;   // 32 x 8
    #pragma unroll
    for (int r = 0; r < 4; r++)
        tile[ty + 8 * r][tx] = W[(size_t)(k0 + ty + 8 * r) * G4 + n0 + tx];
    __syncthreads();
    #pragma unroll
    for (int r = 0; r < 4; r++) {
        float v = tile[tx][ty + 8 * r];
        __nv_bfloat16 hi = __float2bfloat16(v);
        __nv_bfloat16 lo = __float2bfloat16(v - __bfloat162float(hi));
        size_t o = (size_t)(n0 + ty + 8 * r) * INP + k0 + tx;
        g_whi[o] = hi;
        g_wlo[o] = lo;
    }
}

// ---------------- phase 1: mma.sync bf16 hi/lo GEMM (unchanged) ----------------
#define GEMM_SMEM_BYTES (1024 + 2 * 65536)

__global__ __launch_bounds__(256, 1) void xw_tc_kernel(const float* __restrict__ bias)
{
    extern __shared__ char smem[];
    const uint32_t sb = smem_to_u32(smem);
    const int tid  = threadIdx.x;
    const int wid  = tid >> 5;
    const int lane = tid & 31;
    const int n0 = blockIdx.x * 128;
    const int m0 = blockIdx.y * 128;
    float* bias_sm = (float*)smem;

    if (tid < 128) bias_sm[tid] = bias[n0 + tid];

    const int wm = (wid & 1) * 64;
    const int wn = (wid >> 1) * 32;

    const uint32_t aRow = (uint32_t)(lane & 15);
    const uint32_t aCol = (uint32_t)(((lane >> 4) & 1) * 16);
    const uint32_t bRow = (uint32_t)(((lane >> 4) & 1) * 8 + (lane & 7));
    const uint32_t bCol = (uint32_t)(((lane >> 3) & 1) * 16);

    uint32_t aOff[4], bOff[2];
    #pragma unroll
    for (int im = 0; im < 4; im++)
        aOff[im] = (uint32_t)(wm + 16 * im + aRow) * 128 + aCol;
    #pragma unroll
    for (int in_ = 0; in_ < 2; in_++)
        bOff[in_] = (uint32_t)(wn + 16 * in_ + bRow) * 128 + bCol;

    float c[4][4][4];
    #pragma unroll
    for (int i = 0; i < 4; i++)
        #pragma unroll
        for (int j = 0; j < 4; j++)
            #pragma unroll
            for (int k = 0; k < 4; k++) c[i][j][k] = 0.f;

    const int lrow0 = tid >> 3;
    const int lc16  = tid & 7;

    auto issue_chunk = [&](int ch, int buf) {
        const uint32_t bbase = 1024u + (uint32_t)buf * 65536u;
        const int kb = ch * 64;
        #pragma unroll
        for (int it = 0; it < 4; it++) {
            int row = lrow0 + it * 32;
            uint32_t sw = SMEM_SWIZZLE_128B((uint32_t)(row * 128 + lc16 * 16));
            const __nv_bfloat16* gA = g_xhi + (size_t)(m0 + row) * INP + kb + lc16 * 8;
            const __nv_bfloat16* gAl= g_xlo + (size_t)(m0 + row) * INP + kb + lc16 * 8;
            const __nv_bfloat16* gB = g_whi + (size_t)(n0 + row) * INP + kb + lc16 * 8;
            const __nv_bfloat16* gBl= g_wlo + (size_t)(n0 + row) * INP + kb + lc16 * 8;
            cp_async16(sb + bbase +         sw, gA);
            cp_async16(sb + bbase + 16384 + sw, gAl);
            cp_async16(sb + bbase + 32768 + sw, gB);
            cp_async16(sb + bbase + 49152 + sw, gBl);
        }
        cp_async_commit();
    };

    issue_chunk(0, 0);

    for (int ch = 0; ch < 8; ch++) {
        const int buf = ch & 1;
        if (ch < 7) issue_chunk(ch + 1, buf ^ 1);
        if (ch < 7) cp_async_wait<1>(); else cp_async_wait<0>();
        __syncthreads();

        const uint32_t bbase = sb + 1024u + (uint32_t)buf * 65536u;
        #pragma unroll
        for (int ks = 0; ks < 4; ks++) {
            uint32_t ahi[4][4], alo[4][4], bhi[4][4], blo[4][4];
            #pragma unroll
            for (int im = 0; im < 4; im++) {
                uint32_t sw = SMEM_SWIZZLE_128B(aOff[im] + ks * 32);
                ldmatrix_x4(ahi[im], bbase + sw);
                ldmatrix_x4(alo[im], bbase + 16384 + sw);
            }
            #pragma unroll
            for (int ib = 0; ib < 2; ib++) {
                uint32_t sw = SMEM_SWIZZLE_128B(bOff[ib] + ks * 32);
                ldmatrix_x4(bhi[ib], bbase + 32768 + sw);
                ldmatrix_x4(blo[ib], bbase + 49152 + sw);
            }
            #pragma unroll
            for (int im = 0; im < 4; im++) {
                #pragma unroll
                for (int jn = 0; jn < 4; jn++) {
                    uint32_t* bh = &bhi[jn >> 1][(jn & 1) * 2];
                    uint32_t* bl = &blo[jn >> 1][(jn & 1) * 2];
                    mma_bf16(c[im][jn], ahi[im], bh);
                    mma_bf16(c[im][jn], ahi[im], bl);
                    mma_bf16(c[im][jn], alo[im], bh);
                }
            }
        }
        __syncthreads();
    }

    float* cs = (float*)(smem + 1024);   // [128][129]
    const int crow = lane >> 2;
    const int ccol = (lane & 3) * 2;
    #pragma unroll
    for (int im = 0; im < 4; im++) {
        #pragma unroll
        for (int jn = 0; jn < 4; jn++) {
            int r0 = wm + 16 * im + crow;
            int cc = wn + 8 * jn + ccol;
            cs[r0 * 129 + cc]           = c[im][jn][0];
            cs[r0 * 129 + cc + 1]       = c[im][jn][1];
            cs[(r0 + 8) * 129 + cc]     = c[im][jn][2];
            cs[(r0 + 8) * 129 + cc + 1] = c[im][jn][3];
        }
    }
    __syncthreads();

    const int t0 = blockIdx.y * 4;
    for (int i = 0; i < 64; i++) {
        int ro = wid * 64 + i;
        int tl = ro >> 7, n = ro & 127;
        float v = cs[(tl * 32 + lane) * 129 + n] + bias_sm[n];
        g_xw[((size_t)(t0 + tl) * G4 + n0 + n) * BATCH + lane] = v;
    }
}

// ---------------- phase 2: int8 2-limb tensor-core recurrence ------------------
// 128 CTAs x 256 threads (8 warps). CTA owns 4 hidden units -> 16 gate cols.
// h = (q1 + q2/254)/127 (|h|<1); U = s_U*(p1 + p2/254)/127.
// gates*127^2/s_U = SUM q1p1 + (SUM q1p2 + q2p1)/254   (q2p2 dropped, ~2^-16)
// Warp w owns K-chunk w (64 k); issues AND consumes its own cp.asyncs.
// smem chunk rows are 128B = limb1(64B) || limb2(64B), SW128-swizzled.
// smem bytes:
//   [0     .. 32768)  h: 8 chunks of [32 b][128B]
//   [32768 .. 49152)  U: 8 chunks of [16 n][128B]
//   [49152 .. 53248)  xw double buffer, 2 x [16 n][32 b] fp32
//   [53248 .. 71680)  partials [8 w][32 m][18 pad] fp32
#define R_H   0
#define R_U   32768
#define R_XW  49152
#define R_P   53248
#define REC3_SMEM_BYTES 71680
#define NCTA  128

__global__ __launch_bounds__(256, 1) void lstm_rec_tc_kernel(
    const float* __restrict__ U, float* __restrict__ out, int write_tail)
{
    extern __shared__ char smem[];
    const uint32_t sb = smem_to_u32(smem);
    const int tid  = threadIdx.x;
    const int wid  = tid >> 5;
    const int lane = tid & 31;
    const int u0   = blockIdx.x * 4;

    const float s_U = fmaxf(__uint_as_float(g_umax_bits), 1e-30f);
    const float uinv = 127.f / s_U;
    const float sc1 = s_U / 16129.f;          // 1/(127*127) * s_U
    const float sc2 = sc1 / 254.f;

    // ---- quantize U slice -> smem int8 2-limb, chunked+swizzled ----
    for (int i = tid; i < 16 * HID; i += 256) {
        int k = i >> 4, n = i & 15;
        int gcol = u0 + (n & 3) + 512 * (n >> 2);
        float v = U[(size_t)k * G4 + gcol];
        float aq = v * uinv;
        int p1 = __float2int_rn(aq);
        p1 = max(-127, min(127, p1));
        int p2 = __float2int_rn((aq - (float)p1) * 254.f);
        int c = k >> 6, ko = k & 63;
        uint32_t base = (uint32_t)(R_U + c * 2048);
        *(signed char*)(smem + base + SMEM_SWIZZLE_128B((uint32_t)(n * 128 + ko))) =
            (signed char)p1;
        *(signed char*)(smem + base + SMEM_SWIZZLE_128B((uint32_t)(n * 128 + 64 + ko))) =
            (signed char)p2;
    }

    // ldmatrix lane address parts (bytes within a [rows][128B] chunk)
    const uint32_t aRow = (uint32_t)(lane & 15);
    const uint32_t aCol = (uint32_t)(((lane >> 4) & 1) * 16);
    const uint32_t bRow = (uint32_t)(((lane >> 4) & 1) * 8 + (lane & 7));
    const uint32_t bCol = (uint32_t)(((lane >> 3) & 1) * 16);
    uint32_t aBase[2];
    #pragma unroll
    for (int mt = 0; mt < 2; mt++) aBase[mt] = (uint32_t)(mt * 16 + aRow) * 128 + aCol;
    const uint32_t bBase = bRow * 128 + bCol;

    // reduce mapping: thread (tid<128) owns (b = tid>>2, u = tid&3)
    const int rb = tid >> 2;
    const int ua = tid & 3;
    float c_state = 0.f;

    float* p_sm = (float*)(smem + R_P);

    // xw prefetch: warps 4-7 (threads 128..255), slot = t&1
    auto issue_xw = [&](int t) {
        if (tid >= 128) {
            int idx = tid - 128;
            int n = idx >> 3, seg = idx & 7;
            int gcol = u0 + (n & 3) + 512 * (n >> 2);
            cp_async16(sb + R_XW + (uint32_t)((t & 1) * 2048 + n * 128 + seg * 16),
                       g_xw + ((size_t)t * G4 + gcol) * BATCH + seg * 4);
            cp_async_commit();
        }
    };
    // h chunk sub-group load (warp-owned): grp 0 = segs {0,1,4,5} (kt0 data),
    // grp 1 = segs {2,3,6,7} (kt1 data)
    auto issue_h_grp = [&](int R, int cc, int grp) {
        const signed char* hq = g_hq[R];
        #pragma unroll
        for (int j = 0; j < 4; j++) {
            int idx = lane + 32 * j;
            int b = idx >> 2, p = idx & 3;
            int seg = ((p & 1) | ((p & 2) << 1)) + grp * 2;  // {0,1,4,5}+2*grp
            uint32_t sw = SMEM_SWIZZLE_128B((uint32_t)(b * 128 + seg * 16));
            cp_async16(sb + R_H + cc * 4096 + sw, hq + b * 1024 + cc * 128 + seg * 16);
        }
        cp_async_commit();
    };

    __syncthreads();            // U slice ready
    issue_xw(0);

    for (int t = 0; t < T_STEPS; t++) {
        const int R = t & 1;

        // warp w loads chunk w in two staggered groups
        issue_h_grp(R, wid, 0);
        issue_h_grp(R, wid, 1);

        int C1[2][2][4], C2[2][2][4];
        #pragma unroll
        for (int mt = 0; mt < 2; mt++)
            #pragma unroll
            for (int jn = 0; jn < 2; jn++)
                #pragma unroll
                for (int q = 0; q < 4; q++) { C1[mt][jn][q] = 0; C2[mt][jn][q] = 0; }

        const uint32_t hbse = sb + R_H + wid * 4096;
        const uint32_t ubse = sb + R_U + wid * 2048;
        #pragma unroll
        for (int kt = 0; kt < 2; kt++) {
            if (kt == 0) cp_async_wait<1>();   // drains (xw +) grp0
            else         cp_async_wait<0>();   // drains grp1
            uint32_t aq1[2][4], aq2[2][4], bp1[4], bp2[4];
            #pragma unroll
            for (int mt = 0; mt < 2; mt++) {
                ldmatrix_x4(aq1[mt], hbse + SMEM_SWIZZLE_128B(aBase[mt] + kt * 32));
                ldmatrix_x4(aq2[mt], hbse + SMEM_SWIZZLE_128B(aBase[mt] + 64 + kt * 32));
            }
            ldmatrix_x4(bp1, ubse + SMEM_SWIZZLE_128B(bBase + kt * 32));
            ldmatrix_x4(bp2, ubse + SMEM_SWIZZLE_128B(bBase + 64 + kt * 32));
            #pragma unroll
            for (int mt = 0; mt < 2; mt++) {
                #pragma unroll
                for (int jn = 0; jn < 2; jn++) {
                    mma_s8(C1[mt][jn], aq1[mt], &bp1[jn * 2]);
                    mma_s8(C2[mt][jn], aq1[mt], &bp2[jn * 2]);
                    mma_s8(C2[mt][jn], aq2[mt], &bp1[jn * 2]);
                }
            }
        }

        // combine limbs -> float partials [w][m][18]
        {
            const int m  = lane >> 2;
            const int nn = 2 * (lane & 3);
            #pragma unroll
            for (int mt = 0; mt < 2; mt++) {
                #pragma unroll
                for (int jn = 0; jn < 2; jn++) {
                    int row = wid * 32 + mt * 16 + m;
                    int col = jn * 8 + nn;
                    float e0 = (float)C1[mt][jn][0] * sc1 + (float)C2[mt][jn][0] * sc2;
                    float e1 = (float)C1[mt][jn][1] * sc1 + (float)C2[mt][jn][1] * sc2;
                    float e2 = (float)C1[mt][jn][2] * sc1 + (float)C2[mt][jn][2] * sc2;
                    float e3 = (float)C1[mt][jn][3] * sc1 + (float)C2[mt][jn][3] * sc2;
                    *(float2*)&p_sm[row * 18 + col]       = make_float2(e0, e1);
                    *(float2*)&p_sm[(row + 8) * 18 + col] = make_float2(e2, e3);
                }
            }
        }
        __syncthreads();   // partials + xw(t) visible to all threads

        // prefetch xw for next step (different slot than the one being read)
        if (t + 1 < T_STEPS) issue_xw(t + 1);

        // reduce + activations (tid < 128): thread owns (rb, ua)
        if (tid < 128) {
            const float* xw_sm = (const float*)(smem + R_XW + (t & 1) * 2048);
            float s[4];
            #pragma unroll
            for (int g = 0; g < 4; g++) {
                int n = g * 4 + ua;
                float v = xw_sm[n * 32 + rb];
                #pragma unroll
                for (int w = 0; w < 8; w++)
                    v += p_sm[(w * 32 + rb) * 18 + n];
                s[g] = v;
            }
            float ig = sigmoidf_(s[0]);
            float fg = sigmoidf_(s[1]);
            float gg = tanhf(s[2]);
            float og = sigmoidf_(s[3]);
            float cnew = fg * c_state + ig * gg;
            float hnew = og * tanhf(cnew);
            c_state = cnew;

            out[((size_t)t * BATCH + rb) * HID + u0 + ua] = hnew;

            // quantize h -> 2 int8 limbs
            float aq = hnew * 127.f;
            int q1 = __float2int_rn(aq);
            q1 = max(-127, min(127, q1));
            int q2 = __float2int_rn((aq - (float)q1) * 254.f);
            int uu = u0 + ua;
            int cc2 = uu >> 6, ko = uu & 63;
            signed char* dst = g_hq[R ^ 1] + rb * 1024 + cc2 * 128 + ko;
            dst[0]  = (signed char)q1;
            dst[64] = (signed char)q2;

            if (write_tail && t == T_STEPS - 1) {
                out[(size_t)T_STEPS * BATCH * HID + (size_t)rb * HID + u0 + ua] = hnew;
                out[(size_t)T_STEPS * BATCH * HID + BATCH * HID
                    + (size_t)rb * HID + u0 + ua] = cnew;
            }
        }
        __syncthreads();   // h stores complete before the release below

        // grid barrier (single counter, tid0 poll -- R6-proven)
        if (t + 1 < T_STEPS) {
            if (tid == 0) {
                unsigned int target = (unsigned int)NCTA * (unsigned int)(t + 1);
                asm volatile("red.release.gpu.add.u32 [%0], %1;"
                             :: "l"(&g_bar), "r"(1u) : "memory");
                unsigned int v;
                do {
                    asm volatile("ld.acquire.gpu.u32 %0, [%1];"
                                 : "=r"(v) : "l"(&g_bar) : "memory");
                } while (v < target);
            }
            __syncthreads();
        }
    }
}

// ---------------- launch ----------------
extern "C" void kernel_launch(void* const* d_in, const int* in_sizes, int n_in,
                              void* d_out, int out_size)
{
    const float* x    = (const float*)d_in[0]; // (T,B,I)
    const float* W    = (const float*)d_in[1]; // (I,4H)
    const float* U    = (const float*)d_in[2]; // (H,4H)
    const float* bias = (const float*)d_in[3]; // (4H,)
    float* out = (float*)d_out;

    const long long need_tail = (long long)T_STEPS * BATCH * HID + 2LL * BATCH * HID;
    int write_tail = ((long long)out_size >= need_tail) ? 1 : 0;

    static int configured = 0;
    if (!configured) {
        cudaFuncSetAttribute(xw_tc_kernel,
                             cudaFuncAttributeMaxDynamicSharedMemorySize,
                             GEMM_SMEM_BYTES);
        cudaFuncSetAttribute(lstm_rec_tc_kernel,
                             cudaFuncAttributeMaxDynamicSharedMemorySize,
                             REC3_SMEM_BYTES);
        configured = 1;
    }

    lstm_init_kernel<<<64, 256>>>();
    umax_kernel<<<256, 256>>>(U);
    xcvt_kernel<<<(MTOT * INP) / 4 / 256, 256>>>(x);
    wcvt_kernel<<<dim3(G4 / 32, INP / 32), 256>>>(W);
    xw_tc_kernel<<<dim3(16, 256), 256, GEMM_SMEM_BYTES>>>(bias);
    lstm_rec_tc_kernel<<<NCTA, 256, REC3_SMEM_BYTES>>>(U, out, write_tail);
}

// round 9
// speedup vs baseline: 1.2832x; 1.0567x over previous
#include <cuda_runtime.h>
#include <cuda_bf16.h>
#include <math.h>
#include <stdint.h>

#define T_STEPS 1024
#define BATCH   32
#define INP     512
#define HID     512
#define G4      2048   // 4*HID
#define MTOT    (T_STEPS * BATCH)   // 32768

// ---------------- scratch ----------------
__device__ float g_xw[(size_t)T_STEPS * G4 * BATCH]; // [t][col][b]  (256 MB)
__device__ __nv_bfloat16 g_xhi[(size_t)MTOT * INP];  // x hi  [m][k]
__device__ __nv_bfloat16 g_xlo[(size_t)MTOT * INP];  // x lo
__device__ __nv_bfloat16 g_whi[(size_t)G4 * INP];    // W^T hi [n][k]
__device__ __nv_bfloat16 g_wlo[(size_t)G4 * INP];    // W^T lo
__device__ signed char g_hq[2][32 * 1024];           // h 2-limb int8 ping-pong:
                                                     // [ping][b*1024 + c*128 + limb*64 + ko]
__device__ unsigned int g_bar;                       // grid barrier counter
__device__ unsigned int g_umax_bits;                 // max|U| as uint bits

// ================= helpers =================
__device__ __forceinline__ uint32_t smem_to_u32(const void* p) {
    uint32_t a;
    asm("{ .reg .u64 t; cvta.to.shared.u64 t, %1; cvt.u32.u64 %0, t; }"
        : "=r"(a) : "l"(p));
    return a;
}
#define SMEM_SWIZZLE_128B(off) ((off) ^ (((off) >> 3) & 0x70))

__device__ __forceinline__ void cp_async16(uint32_t smem_addr, const void* gptr) {
    asm volatile("cp.async.cg.shared.global [%0], [%1], 16;"
                 :: "r"(smem_addr), "l"(gptr) : "memory");
}
__device__ __forceinline__ void cp_async_commit() {
    asm volatile("cp.async.commit_group;" ::: "memory");
}
template <int N>
__device__ __forceinline__ void cp_async_wait() {
    asm volatile("cp.async.wait_group %0;" :: "n"(N) : "memory");
}

__device__ __forceinline__ void ldmatrix_x4(uint32_t* r, uint32_t addr) {
    asm volatile("ldmatrix.sync.aligned.m8n8.x4.shared.b16 {%0,%1,%2,%3}, [%4];"
                 : "=r"(r[0]), "=r"(r[1]), "=r"(r[2]), "=r"(r[3]) : "r"(addr));
}
__device__ __forceinline__ void mma_bf16(float* c, const uint32_t* a, const uint32_t* b) {
    asm volatile(
        "mma.sync.aligned.m16n8k16.row.col.f32.bf16.bf16.f32 "
        "{%0,%1,%2,%3}, {%4,%5,%6,%7}, {%8,%9}, {%0,%1,%2,%3};"
        : "+f"(c[0]), "+f"(c[1]), "+f"(c[2]), "+f"(c[3])
        : "r"(a[0]), "r"(a[1]), "r"(a[2]), "r"(a[3]), "r"(b[0]), "r"(b[1]));
}
__device__ __forceinline__ void mma_s8(int* c, const uint32_t* a, const uint32_t* b) {
    asm volatile(
        "mma.sync.aligned.m16n8k32.row.col.s32.s8.s8.s32 "
        "{%0,%1,%2,%3}, {%4,%5,%6,%7}, {%8,%9}, {%0,%1,%2,%3};"
        : "+r"(c[0]), "+r"(c[1]), "+r"(c[2]), "+r"(c[3])
        : "r"(a[0]), "r"(a[1]), "r"(a[2]), "r"(a[3]), "r"(b[0]), "r"(b[1]));
}
__device__ __forceinline__ float sigmoidf_(float v) {
    return 1.f / (1.f + __expf(-v));
}

// ---------------- init ----------------
__global__ void lstm_init_kernel() {
    int idx = blockIdx.x * blockDim.x + threadIdx.x;
    int n = 2 * 32 * 1024 / 4;
    for (int i = idx; i < n; i += gridDim.x * blockDim.x)
        ((int*)g_hq)[i] = 0;
    if (idx == 0) { g_bar = 0u; g_umax_bits = 0u; }
}

// ---------------- max|U| reduction ----------------
__global__ __launch_bounds__(256) void umax_kernel(const float* __restrict__ U) {
    __shared__ float red[256];
    float m = 0.f;
    int n = G4 * INP;
    for (int i = blockIdx.x * 256 + threadIdx.x; i < n; i += gridDim.x * 256)
        m = fmaxf(m, fabsf(U[i]));
    red[threadIdx.x] = m;
    __syncthreads();
    for (int s = 128; s > 0; s >>= 1) {
        if (threadIdx.x < s) red[threadIdx.x] = fmaxf(red[threadIdx.x], red[threadIdx.x + s]);
        __syncthreads();
    }
    if (threadIdx.x == 0)
        atomicMax(&g_umax_bits, __float_as_uint(red[0]));
}

// ---------------- convert x -> bf16 hi/lo ----------------
__global__ __launch_bounds__(256) void xcvt_kernel(const float* __restrict__ x) {
    size_t i = ((size_t)blockIdx.x * 256 + threadIdx.x) * 4;
    float4 v = *(const float4*)(x + i);
    __nv_bfloat16 h0 = __float2bfloat16(v.x), h1 = __float2bfloat16(v.y),
                  h2 = __float2bfloat16(v.z), h3 = __float2bfloat16(v.w);
    __nv_bfloat16 l0 = __float2bfloat16(v.x - __bfloat162float(h0));
    __nv_bfloat16 l1 = __float2bfloat16(v.y - __bfloat162float(h1));
    __nv_bfloat16 l2 = __float2bfloat16(v.z - __bfloat162float(h2));
    __nv_bfloat16 l3 = __float2bfloat16(v.w - __bfloat162float(h3));
    __nv_bfloat162* ph = (__nv_bfloat162*)(g_xhi + i);
    __nv_bfloat162* pl = (__nv_bfloat162*)(g_xlo + i);
    ph[0] = __nv_bfloat162(h0, h1); ph[1] = __nv_bfloat162(h2, h3);
    pl[0] = __nv_bfloat162(l0, l1); pl[1] = __nv_bfloat162(l2, l3);
}

// ---------------- convert + transpose W -> [n][k] bf16 hi/lo ----------------
__global__ __launch_bounds__(256) void wcvt_kernel(const float* __restrict__ W) {
    __shared__ float tile[32][33];
    int n0 = blockIdx.x * 32, k0 = blockIdx.y * 32;
    int tx = threadIdx.x & 31, ty = threadIdx.x >> 5;   // 32 x 8
    #pragma unroll
    for (int r = 0; r < 4; r++)
        tile[ty + 8 * r][tx] = W[(size_t)(k0 + ty + 8 * r) * G4 + n0 + tx];
    __syncthreads();
    #pragma unroll
    for (int r = 0; r < 4; r++) {
        float v = tile[tx][ty + 8 * r];
        __nv_bfloat16 hi = __float2bfloat16(v);
        __nv_bfloat16 lo = __float2bfloat16(v - __bfloat162float(hi));
        size_t o = (size_t)(n0 + ty + 8 * r) * INP + k0 + tx;
        g_whi[o] = hi;
        g_wlo[o] = lo;
    }
}

// ---------------- phase 1: mma.sync bf16 hi/lo GEMM (unchanged) ----------------
#define GEMM_SMEM_BYTES (1024 + 2 * 65536)

__global__ __launch_bounds__(256, 1) void xw_tc_kernel(const float* __restrict__ bias)
{
    extern __shared__ char smem[];
    const uint32_t sb = smem_to_u32(smem);
    const int tid  = threadIdx.x;
    const int wid  = tid >> 5;
    const int lane = tid & 31;
    const int n0 = blockIdx.x * 128;
    const int m0 = blockIdx.y * 128;
    float* bias_sm = (float*)smem;

    if (tid < 128) bias_sm[tid] = bias[n0 + tid];

    const int wm = (wid & 1) * 64;
    const int wn = (wid >> 1) * 32;

    const uint32_t aRow = (uint32_t)(lane & 15);
    const uint32_t aCol = (uint32_t)(((lane >> 4) & 1) * 16);
    const uint32_t bRow = (uint32_t)(((lane >> 4) & 1) * 8 + (lane & 7));
    const uint32_t bCol = (uint32_t)(((lane >> 3) & 1) * 16);

    uint32_t aOff[4], bOff[2];
    #pragma unroll
    for (int im = 0; im < 4; im++)
        aOff[im] = (uint32_t)(wm + 16 * im + aRow) * 128 + aCol;
    #pragma unroll
    for (int in_ = 0; in_ < 2; in_++)
        bOff[in_] = (uint32_t)(wn + 16 * in_ + bRow) * 128 + bCol;

    float c[4][4][4];
    #pragma unroll
    for (int i = 0; i < 4; i++)
        #pragma unroll
        for (int j = 0; j < 4; j++)
            #pragma unroll
            for (int k = 0; k < 4; k++) c[i][j][k] = 0.f;

    const int lrow0 = tid >> 3;
    const int lc16  = tid & 7;

    auto issue_chunk = [&](int ch, int buf) {
        const uint32_t bbase = 1024u + (uint32_t)buf * 65536u;
        const int kb = ch * 64;
        #pragma unroll
        for (int it = 0; it < 4; it++) {
            int row = lrow0 + it * 32;
            uint32_t sw = SMEM_SWIZZLE_128B((uint32_t)(row * 128 + lc16 * 16));
            const __nv_bfloat16* gA = g_xhi + (size_t)(m0 + row) * INP + kb + lc16 * 8;
            const __nv_bfloat16* gAl= g_xlo + (size_t)(m0 + row) * INP + kb + lc16 * 8;
            const __nv_bfloat16* gB = g_whi + (size_t)(n0 + row) * INP + kb + lc16 * 8;
            const __nv_bfloat16* gBl= g_wlo + (size_t)(n0 + row) * INP + kb + lc16 * 8;
            cp_async16(sb + bbase +         sw, gA);
            cp_async16(sb + bbase + 16384 + sw, gAl);
            cp_async16(sb + bbase + 32768 + sw, gB);
            cp_async16(sb + bbase + 49152 + sw, gBl);
        }
        cp_async_commit();
    };

    issue_chunk(0, 0);

    for (int ch = 0; ch < 8; ch++) {
        const int buf = ch & 1;
        if (ch < 7) issue_chunk(ch + 1, buf ^ 1);
        if (ch < 7) cp_async_wait<1>(); else cp_async_wait<0>();
        __syncthreads();

        const uint32_t bbase = sb + 1024u + (uint32_t)buf * 65536u;
        #pragma unroll
        for (int ks = 0; ks < 4; ks++) {
            uint32_t ahi[4][4], alo[4][4], bhi[4][4], blo[4][4];
            #pragma unroll
            for (int im = 0; im < 4; im++) {
                uint32_t sw = SMEM_SWIZZLE_128B(aOff[im] + ks * 32);
                ldmatrix_x4(ahi[im], bbase + sw);
                ldmatrix_x4(alo[im], bbase + 16384 + sw);
            }
            #pragma unroll
            for (int ib = 0; ib < 2; ib++) {
                uint32_t sw = SMEM_SWIZZLE_128B(bOff[ib] + ks * 32);
                ldmatrix_x4(bhi[ib], bbase + 32768 + sw);
                ldmatrix_x4(blo[ib], bbase + 49152 + sw);
            }
            #pragma unroll
            for (int im = 0; im < 4; im++) {
                #pragma unroll
                for (int jn = 0; jn < 4; jn++) {
                    uint32_t* bh = &bhi[jn >> 1][(jn & 1) * 2];
                    uint32_t* bl = &blo[jn >> 1][(jn & 1) * 2];
                    mma_bf16(c[im][jn], ahi[im], bh);
                    mma_bf16(c[im][jn], ahi[im], bl);
                    mma_bf16(c[im][jn], alo[im], bh);
                }
            }
        }
        __syncthreads();
    }

    float* cs = (float*)(smem + 1024);   // [128][129]
    const int crow = lane >> 2;
    const int ccol = (lane & 3) * 2;
    #pragma unroll
    for (int im = 0; im < 4; im++) {
        #pragma unroll
        for (int jn = 0; jn < 4; jn++) {
            int r0 = wm + 16 * im + crow;
            int cc = wn + 8 * jn + ccol;
            cs[r0 * 129 + cc]           = c[im][jn][0];
            cs[r0 * 129 + cc + 1]       = c[im][jn][1];
            cs[(r0 + 8) * 129 + cc]     = c[im][jn][2];
            cs[(r0 + 8) * 129 + cc + 1] = c[im][jn][3];
        }
    }
    __syncthreads();

    const int t0 = blockIdx.y * 4;
    for (int i = 0; i < 64; i++) {
        int ro = wid * 64 + i;
        int tl = ro >> 7, n = ro & 127;
        float v = cs[(tl * 32 + lane) * 129 + n] + bias_sm[n];
        g_xw[((size_t)(t0 + tl) * G4 + n0 + n) * BATCH + lane] = v;
    }
}

// ---------------- phase 2: int8 recurrence, batch-split blocking ---------------
// 128 CTAs x 256 threads. CTA = (unit-group ug = bid>>1, batch-half bh = bid&1):
// owns 8 hidden units (32 gate cols, gate-major n = g*8+u) x 16 batches.
// Warp w owns K-chunk w (64 k, both limbs); issues AND consumes its own cp.asyncs.
// smem bytes:
//   [0     .. 16384)  h: 8 chunks of [16 b][128B = limb1|limb2], SW128
//   [16384 .. 49152)  U: 8 chunks of [32 n][128B]
//   [49152 .. 54272)  xw double buffer, 2 x [32 n][20 f] (stride 80B, 16 data)
//   [54272 .. 74752)  partials [8 w][16 m][40 f]
#define R_H   0
#define R_U   16384
#define R_XW  49152
#define R_P   54272
#define REC4_SMEM_BYTES 74752
#define NCTA  128

__global__ __launch_bounds__(256, 1) void lstm_rec_tc_kernel(
    const float* __restrict__ U, float* __restrict__ out, int write_tail)
{
    extern __shared__ char smem[];
    const uint32_t sb = smem_to_u32(smem);
    const int tid  = threadIdx.x;
    const int wid  = tid >> 5;
    const int lane = tid & 31;
    const int u0   = (blockIdx.x >> 1) * 8;      // unit group
    const int b0   = (blockIdx.x & 1) * 16;      // batch half

    const float s_U = fmaxf(__uint_as_float(g_umax_bits), 1e-30f);
    const float uinv = 127.f / s_U;
    const float sc1 = s_U / 16129.f;
    const float sc2 = sc1 / 254.f;

    // ---- quantize U slice -> smem int8 2-limb, chunked+swizzled ----
    for (int i = tid; i < 32 * HID; i += 256) {
        int k = i >> 5, n = i & 31;
        int gcol = u0 + (n & 7) + 512 * (n >> 3);
        float v = U[(size_t)k * G4 + gcol];
        float aq = v * uinv;
        int p1 = __float2int_rn(aq);
        p1 = max(-127, min(127, p1));
        int p2 = __float2int_rn((aq - (float)p1) * 254.f);
        int c = k >> 6, ko = k & 63;
        uint32_t base = (uint32_t)(R_U + c * 4096);
        *(signed char*)(smem + base + SMEM_SWIZZLE_128B((uint32_t)(n * 128 + ko))) =
            (signed char)p1;
        *(signed char*)(smem + base + SMEM_SWIZZLE_128B((uint32_t)(n * 128 + 64 + ko))) =
            (signed char)p2;
    }

    // ldmatrix lane address parts
    const uint32_t aRow = (uint32_t)(lane & 15);
    const uint32_t aCol = (uint32_t)(((lane >> 4) & 1) * 16);
    const uint32_t bRow = (uint32_t)(((lane >> 4) & 1) * 8 + (lane & 7));
    const uint32_t bCol = (uint32_t)(((lane >> 3) & 1) * 16);
    const uint32_t aBase = aRow * 128 + aCol;    // one m-tile (16 batches)
    const uint32_t bBase = bRow * 128 + bCol;    // n-tiles 0-1; +2048 for 2-3

    // activation mapping: thread (tid<128) owns (b = b0 + (tid>>3), u = tid&7)
    const int rb = tid >> 3;
    const int ua = tid & 7;
    float c_state = 0.f;

    float* p_sm = (float*)(smem + R_P);

    // xw prefetch: threads 0..127, 1 cp.async16 each; ALL threads commit
    auto issue_xw = [&](int t, int valid) {
        if (valid && tid < 128) {
            int n = tid >> 2, seg = tid & 3;
            int gcol = u0 + (n & 7) + 512 * (n >> 3);
            cp_async16(sb + R_XW + (uint32_t)((t & 1) * 2560 + n * 80 + seg * 16),
                       g_xw + ((size_t)t * G4 + gcol) * BATCH + b0 + seg * 4);
        }
        cp_async_commit();
    };
    // h chunk load: warp w loads chunk w, 4 cp/lane (16 rows x 8 segs)
    auto issue_h_chunk = [&](int R, int cc) {
        const signed char* hq = g_hq[R];
        #pragma unroll
        for (int j = 0; j < 4; j++) {
            int idx = lane + 32 * j;
            int b = idx >> 3, seg = idx & 7;
            uint32_t sw = SMEM_SWIZZLE_128B((uint32_t)(b * 128 + seg * 16));
            cp_async16(sb + R_H + cc * 2048 + sw,
                       hq + (b0 + b) * 1024 + cc * 128 + seg * 16);
        }
        cp_async_commit();
    };

    __syncthreads();            // U slice ready
    issue_xw(0, 1);

    for (int t = 0; t < T_STEPS; t++) {
        const int R = t & 1;

        issue_h_chunk(R, wid);              // group: h(t) chunk w
        issue_xw(t + 1, t + 1 < T_STEPS);   // group: xw(t+1) (maybe empty)
        cp_async_wait<1>();                 // drain everything except xw(t+1)

        int C1[4][4], C2[4][4];
        #pragma unroll
        for (int nt = 0; nt < 4; nt++)
            #pragma unroll
            for (int q = 0; q < 4; q++) { C1[nt][q] = 0; C2[nt][q] = 0; }

        const uint32_t hbse = sb + R_H + wid * 2048;
        const uint32_t ubse = sb + R_U + wid * 4096;
        #pragma unroll
        for (int kt = 0; kt < 2; kt++) {
            uint32_t aq1[4], aq2[4], bp1a[4], bp2a[4], bp1b[4], bp2b[4];
            ldmatrix_x4(aq1, hbse + SMEM_SWIZZLE_128B(aBase + kt * 32));
            ldmatrix_x4(aq2, hbse + SMEM_SWIZZLE_128B(aBase + 64 + kt * 32));
            ldmatrix_x4(bp1a, ubse + SMEM_SWIZZLE_128B(bBase + kt * 32));
            ldmatrix_x4(bp2a, ubse + SMEM_SWIZZLE_128B(bBase + 64 + kt * 32));
            ldmatrix_x4(bp1b, ubse + 2048 + SMEM_SWIZZLE_128B(bBase + kt * 32));
            ldmatrix_x4(bp2b, ubse + 2048 + SMEM_SWIZZLE_128B(bBase + 64 + kt * 32));
            #pragma unroll
            for (int nt = 0; nt < 4; nt++) {
                uint32_t* b1 = (nt < 2) ? &bp1a[(nt & 1) * 2] : &bp1b[(nt & 1) * 2];
                uint32_t* b2 = (nt < 2) ? &bp2a[(nt & 1) * 2] : &bp2b[(nt & 1) * 2];
                mma_s8(C1[nt], aq1, b1);
                mma_s8(C2[nt], aq1, b2);
                mma_s8(C2[nt], aq2, b1);
            }
        }

        // combine limbs -> float partials [w][16 m][40]
        {
            const int m  = lane >> 2;
            const int nn = 2 * (lane & 3);
            #pragma unroll
            for (int nt = 0; nt < 4; nt++) {
                int col = nt * 8 + nn;
                float e0 = (float)C1[nt][0] * sc1 + (float)C2[nt][0] * sc2;
                float e1 = (float)C1[nt][1] * sc1 + (float)C2[nt][1] * sc2;
                float e2 = (float)C1[nt][2] * sc1 + (float)C2[nt][2] * sc2;
                float e3 = (float)C1[nt][3] * sc1 + (float)C2[nt][3] * sc2;
                *(float2*)&p_sm[(wid * 16 + m) * 40 + col]     = make_float2(e0, e1);
                *(float2*)&p_sm[(wid * 16 + m + 8) * 40 + col] = make_float2(e2, e3);
            }
        }
        __syncthreads();   // partials + xw(t) visible to all threads

        // reduce + activations (tid < 128): thread owns (rb, ua)
        if (tid < 128) {
            const float* xw_sm = (const float*)(smem + R_XW + (t & 1) * 2560);
            float s[4];
            #pragma unroll
            for (int g = 0; g < 4; g++) {
                int n = g * 8 + ua;
                float v = xw_sm[n * 20 + rb];
                #pragma unroll
                for (int w = 0; w < 8; w++)
                    v += p_sm[(w * 16 + rb) * 40 + n];
                s[g] = v;
            }
            float ig = sigmoidf_(s[0]);
            float fg = sigmoidf_(s[1]);
            float gg = tanhf(s[2]);
            float og = sigmoidf_(s[3]);
            float cnew = fg * c_state + ig * gg;
            float hnew = og * tanhf(cnew);
            c_state = cnew;

            const int b = b0 + rb;
            out[((size_t)t * BATCH + b) * HID + u0 + ua] = hnew;

            // quantize h -> 2 int8 limbs
            float aq = hnew * 127.f;
            int q1 = __float2int_rn(aq);
            q1 = max(-127, min(127, q1));
            int q2 = __float2int_rn((aq - (float)q1) * 254.f);
            int uu = u0 + ua;
            int cc2 = uu >> 6, ko = uu & 63;
            signed char* dst = g_hq[R ^ 1] + b * 1024 + cc2 * 128 + ko;
            dst[0]  = (signed char)q1;
            dst[64] = (signed char)q2;

            if (write_tail && t == T_STEPS - 1) {
                out[(size_t)T_STEPS * BATCH * HID + (size_t)b * HID + u0 + ua] = hnew;
                out[(size_t)T_STEPS * BATCH * HID + BATCH * HID
                    + (size_t)b * HID + u0 + ua] = cnew;
            }
        }
        __syncthreads();   // h stores complete before the release below

        // grid barrier (single counter, tid0 poll)
        if (t + 1 < T_STEPS) {
            if (tid == 0) {
                unsigned int target = (unsigned int)NCTA * (unsigned int)(t + 1);
                asm volatile("red.release.gpu.add.u32 [%0], %1;"
                             :: "l"(&g_bar), "r"(1u) : "memory");
                unsigned int v;
                do {
                    asm volatile("ld.acquire.gpu.u32 %0, [%1];"
                                 : "=r"(v) : "l"(&g_bar) : "memory");
                } while (v < target);
            }
            __syncthreads();
        }
    }
}

// ---------------- launch ----------------
extern "C" void kernel_launch(void* const* d_in, const int* in_sizes, int n_in,
                              void* d_out, int out_size)
{
    const float* x    = (const float*)d_in[0]; // (T,B,I)
    const float* W    = (const float*)d_in[1]; // (I,4H)
    const float* U    = (const float*)d_in[2]; // (H,4H)
    const float* bias = (const float*)d_in[3]; // (4H,)
    float* out = (float*)d_out;

    const long long need_tail = (long long)T_STEPS * BATCH * HID + 2LL * BATCH * HID;
    int write_tail = ((long long)out_size >= need_tail) ? 1 : 0;

    static int configured = 0;
    if (!configured) {
        cudaFuncSetAttribute(xw_tc_kernel,
                             cudaFuncAttributeMaxDynamicSharedMemorySize,
                             GEMM_SMEM_BYTES);
        cudaFuncSetAttribute(lstm_rec_tc_kernel,
                             cudaFuncAttributeMaxDynamicSharedMemorySize,
                             REC4_SMEM_BYTES);
        configured = 1;
    }

    lstm_init_kernel<<<64, 256>>>();
    umax_kernel<<<256, 256>>>(U);
    xcvt_kernel<<<(MTOT * INP) / 4 / 256, 256>>>(x);
    wcvt_kernel<<<dim3(G4 / 32, INP / 32), 256>>>(W);
    xw_tc_kernel<<<dim3(16, 256), 256, GEMM_SMEM_BYTES>>>(bias);
    lstm_rec_tc_kernel<<<NCTA, 256, REC4_SMEM_BYTES>>>(U, out, write_tail);
}